// round 11
// baseline (speedup 1.0000x reference)
#include <cuda_runtime.h>
#include <math.h>

#define BB  16
#define CC  64
#define HH  128
#define WW  128
#define HW  (HH*WW)
#define BC  (BB*CC)

// Per-(b,c) x-space threshold T = logit(sigmoid(max x) - 0.01).
__device__ float g_T[BC];
// Order-preserving encoded per-plane max (atomicMax target). memset to 0 each launch.
__device__ unsigned g_enc[BC];
// Per-(bc, row-group) bbox partial sums: [bc][rg][5] = S, Sc, Sr, Sw, Sh.
__device__ float g_bbp[BC * 16 * 5];

__device__ __forceinline__ float sigmoidf_(float v) {
    return 1.0f / (1.0f + expf(-v));
}
__device__ __forceinline__ unsigned enc_f(float f) {
    unsigned u = __float_as_uint(f);
    return (u & 0x80000000u) ? ~u : (u | 0x80000000u);
}
__device__ __forceinline__ float dec_f(unsigned k) {
    unsigned u = (k & 0x80000000u) ? (k & 0x7FFFFFFFu) : ~k;
    return __uint_as_float(u);
}

// ---------------------------------------------------------------------------
// K1a: plane max, 4 segment-blocks per plane, atomicMax on encoded key.
// ---------------------------------------------------------------------------
__global__ __launch_bounds__(256) void k1a_max(const float* __restrict__ x)
{
    const int bc  = blockIdx.x >> 2;
    const int seg = blockIdx.x & 3;
    const int t   = threadIdx.x;
    const float4* xp = (const float4*)(x + (size_t)bc * HW) + seg * 1024;

    float mx = -INFINITY;
    #pragma unroll
    for (int j = 0; j < 4; ++j) {
        float4 v = __ldg(xp + j * 256 + t);
        mx = fmaxf(fmaxf(fmaxf(mx, v.x), fmaxf(v.y, v.z)), v.w);
    }
    #pragma unroll
    for (int o = 16; o; o >>= 1) mx = fmaxf(mx, __shfl_xor_sync(0xffffffffu, mx, o));
    __shared__ float red[8];
    if ((t & 31) == 0) red[t >> 5] = mx;
    __syncthreads();
    if (t == 0) {
        float v = red[0];
        #pragma unroll
        for (int k = 1; k < 8; ++k) v = fmaxf(v, red[k]);
        atomicMax(&g_enc[bc], enc_f(v));
    }
}

// ---------------------------------------------------------------------------
// K1b: decode max -> ps, T. Writes g_T and bbox cols 0,5.
// ---------------------------------------------------------------------------
__global__ __launch_bounds__(256) void k1b_thresh(float* __restrict__ out)
{
    const int bc = blockIdx.x * 256 + threadIdx.x;
    if (bc >= BC) return;
    float v  = dec_f(g_enc[bc]);
    float ps = sigmoidf_(v);
    float M  = ps - 0.01f;
    float T;
    if (M > 0.0f) {
        double dM = (double)M;
        T = (float)log(dM / (1.0 - dM));
    } else {
        T = -INFINITY;
    }
    g_T[bc] = T;
    float* bb = out + (size_t)BB * 3 * CC * HW + (size_t)bc * 6;
    bb[0] = (float)(bc / CC);
    bb[5] = ps;
}

// ---------------------------------------------------------------------------
// K2 fused conv/argmax (round-9 winner) + embedded bbox partial sums.
// Masked pixels are rare: ballot-guarded warp reductions into per-(channel,
// warp) smem slots; fixed-order block reduce at the end -> g_bbp[bc][rg][5].
// ---------------------------------------------------------------------------
#define RG 8
#define TR 18
#define TP 144
#define NFILL 9
#define TILE_SZ (TR * TP)
#define SACC_N (5 * CC * 8)     // 5 quantities x 64 channels x 8 warps

__global__ __launch_bounds__(256, 2) void k2_fused(
    const float* __restrict__ x,
    const float* __restrict__ w_bbx,
    const float* __restrict__ w_width,
    const float* __restrict__ w_width_sh,
    const float* __restrict__ w_height,
    const float* __restrict__ w_height_sh,
    float* __restrict__ out)
{
    __shared__ float tile[4][TILE_SZ];   // ring of 4 (2 pairs)
    __shared__ float scw[CC * 11], sch[CC * 11];
    __shared__ float ssW[CC], ssH[CC], sTv[CC];
    __shared__ float sacc[SACC_N];       // [q][c][warp]

    const int t    = threadIdx.x;
    const int lane = t & 31;
    const int warp = t >> 5;
    const int b    = blockIdx.x >> 4;
    const int rg   = blockIdx.x & 15;
    const int row0 = rg * RG;
    const int r    = warp;               // 0..7
    const int c4   = (t & 31) << 2;      // 0..124
    const int grow = row0 + r;
    const float growf = (float)grow;

    for (int i = t; i < TILE_SZ; i += 256) {
        int col = i % TP;
        if (col < 8 || col >= 136) {
            tile[0][i] = 0.f; tile[1][i] = 0.f; tile[2][i] = 0.f; tile[3][i] = 0.f;
        }
    }
    for (int i = t; i < CC * 11; i += 256) { scw[i] = w_width[i]; sch[i] = w_height[i]; }
    for (int i = t; i < SACC_N; i += 256) sacc[i] = 0.f;
    if (t < CC) {
        float s0 = w_bbx[t] * 128.0f;
        ssW[t] = s0 * w_width_sh[t];
        ssH[t] = s0 * w_height_sh[t];
        sTv[t] = g_T[b * CC + t];
    }

    int   fidx[NFILL];
    bool  fok[NFILL];
    int   goff[NFILL];
    #pragma unroll
    for (int j = 0; j < NFILL; ++j) {
        int idx = t + j * 256;
        fidx[j] = (idx >> 7) * TP + 8 + (idx & 127);
        int gr  = row0 - 5 + (idx >> 7);
        fok[j]  = (gr >= 0 && gr < HH);
        goff[j] = (gr << 7) + (idx & 127);
    }

    float regs[2][NFILL];
    const float* xp0 = x + (size_t)(b * CC) * HW;

    #pragma unroll
    for (int p = 0; p < 2; ++p) {
        const float* xp = xp0 + (size_t)p * HW;
        #pragma unroll
        for (int j = 0; j < NFILL; ++j)
            regs[p][j] = fok[j] ? __ldg(xp + goff[j]) : 0.f;
        #pragma unroll
        for (int j = 0; j < NFILL; ++j)
            tile[p][fidx[j]] = regs[p][j];
    }

    float mS[4], mW[4], mH[4];
    int   iS[4], iW[4], iH[4];
    #pragma unroll
    for (int j = 0; j < 4; ++j) {
        mS[j] = -INFINITY; mW[j] = -INFINITY; mH[j] = -INFINITY;
        iS[j] = 0; iW[j] = 0; iH[j] = 0;
    }

    for (int cp = 0; cp < CC / 2; ++cp) {
        const int cur = (cp & 1) << 1;
        const int c0 = 2 * cp, c1 = 2 * cp + 1;

        if (cp + 1 < CC / 2) {
            #pragma unroll
            for (int p = 0; p < 2; ++p) {
                const float* xp = xp0 + (size_t)(2 * cp + 2 + p) * HW;
                #pragma unroll
                for (int j = 0; j < NFILL; ++j)
                    regs[p][j] = fok[j] ? __ldg(xp + goff[j]) : 0.f;
            }
        }
        __syncthreads();

        const float* tl0 = tile[cur];
        const float* tl1 = tile[cur + 1];

        float in0[20], in1[20];
        {
            const float* h0 = &tl0[(r + 5) * TP + c4];
            const float* h1 = &tl1[(r + 5) * TP + c4];
            #pragma unroll
            for (int m = 0; m < 5; ++m) {
                float4 v0 = *(const float4*)(h0 + 4 * m);
                float4 v1 = *(const float4*)(h1 + 4 * m);
                in0[4*m+0] = v0.x; in0[4*m+1] = v0.y; in0[4*m+2] = v0.z; in0[4*m+3] = v0.w;
                in1[4*m+0] = v1.x; in1[4*m+1] = v1.y; in1[4*m+2] = v1.z; in1[4*m+3] = v1.w;
            }
        }
        float hv0[4] = {0.f,0.f,0.f,0.f}, hv1[4] = {0.f,0.f,0.f,0.f};
        #pragma unroll
        for (int k = 0; k < 11; ++k) {
            float4 v0 = *(const float4*)(&tl0[(r + k) * TP + 8 + c4]);
            float4 v1 = *(const float4*)(&tl1[(r + k) * TP + 8 + c4]);
            float ck0 = sch[c0 * 11 + k];
            float ck1 = sch[c1 * 11 + k];
            hv0[0] = fmaf(v0.x, ck0, hv0[0]);  hv1[0] = fmaf(v1.x, ck1, hv1[0]);
            hv0[1] = fmaf(v0.y, ck0, hv0[1]);  hv1[1] = fmaf(v1.y, ck1, hv1[1]);
            hv0[2] = fmaf(v0.z, ck0, hv0[2]);  hv1[2] = fmaf(v1.z, ck1, hv1[2]);
            hv0[3] = fmaf(v0.w, ck0, hv0[3]);  hv1[3] = fmaf(v1.w, ck1, hv1[3]);
        }
        float wv0[4] = {0.f,0.f,0.f,0.f}, wv1[4] = {0.f,0.f,0.f,0.f};
        #pragma unroll
        for (int k = 0; k < 11; ++k) {
            float ck0 = scw[c0 * 11 + k];
            float ck1 = scw[c1 * 11 + k];
            wv0[0] = fmaf(in0[3 + k], ck0, wv0[0]);  wv1[0] = fmaf(in1[3 + k], ck1, wv1[0]);
            wv0[1] = fmaf(in0[4 + k], ck0, wv0[1]);  wv1[1] = fmaf(in1[4 + k], ck1, wv1[1]);
            wv0[2] = fmaf(in0[5 + k], ck0, wv0[2]);  wv1[2] = fmaf(in1[5 + k], ck1, wv1[2]);
            wv0[3] = fmaf(in0[6 + k], ck0, wv0[3]);  wv1[3] = fmaf(in1[6 + k], ck1, wv1[3]);
        }
        {
            const float sW0 = ssW[c0], sH0 = ssH[c0], T0 = sTv[c0];
            const float sW1 = ssW[c1], sH1 = ssH[c1], T1 = sTv[c1];
            bool  m0 = false, m1 = false;
            float pS0=0.f,pC0=0.f,pR0=0.f,pW0=0.f,pH0=0.f;
            float pS1=0.f,pC1=0.f,pR1=0.f,pW1=0.f,pH1=0.f;
            #pragma unroll
            for (int j = 0; j < 4; ++j) {
                float w0 = wv0[j] * sW0, w1 = wv1[j] * sW1;
                float h0 = hv0[j] * sH0, h1 = hv1[j] * sH1;
                float x0 = in0[8 + j],   x1 = in1[8 + j];
                float s0 = (x0 > T0) ? x0 : 0.f;
                float s1 = (x1 > T1) ? x1 : 0.f;
                if (s0 > mS[j]) { mS[j] = s0; iS[j] = c0; }
                if (w0 > mW[j]) { mW[j] = w0; iW[j] = c0; }
                if (h0 > mH[j]) { mH[j] = h0; iH[j] = c0; }
                if (s1 > mS[j]) { mS[j] = s1; iS[j] = c1; }
                if (w1 > mW[j]) { mW[j] = w1; iW[j] = c1; }
                if (h1 > mH[j]) { mH[j] = h1; iH[j] = c1; }
                if (x0 > T0) {
                    m0 = true;
                    pS0 += x0; pC0 += (float)(c4 + j) * x0; pR0 += growf * x0;
                    pW0 += w0 * x0; pH0 += h0 * x0;
                }
                if (x1 > T1) {
                    m1 = true;
                    pS1 += x1; pC1 += (float)(c4 + j) * x1; pR1 += growf * x1;
                    pW1 += w1 * x1; pH1 += h1 * x1;
                }
            }
            // rare-path warp reductions (uniform branches via ballot)
            if (__ballot_sync(0xffffffffu, m0)) {
                #pragma unroll
                for (int o = 16; o; o >>= 1) {
                    pS0 += __shfl_xor_sync(0xffffffffu, pS0, o);
                    pC0 += __shfl_xor_sync(0xffffffffu, pC0, o);
                    pR0 += __shfl_xor_sync(0xffffffffu, pR0, o);
                    pW0 += __shfl_xor_sync(0xffffffffu, pW0, o);
                    pH0 += __shfl_xor_sync(0xffffffffu, pH0, o);
                }
                if (lane == 0) {
                    int s = c0 * 8 + warp;
                    sacc[0*512 + s] += pS0; sacc[1*512 + s] += pC0;
                    sacc[2*512 + s] += pR0; sacc[3*512 + s] += pW0;
                    sacc[4*512 + s] += pH0;
                }
            }
            if (__ballot_sync(0xffffffffu, m1)) {
                #pragma unroll
                for (int o = 16; o; o >>= 1) {
                    pS1 += __shfl_xor_sync(0xffffffffu, pS1, o);
                    pC1 += __shfl_xor_sync(0xffffffffu, pC1, o);
                    pR1 += __shfl_xor_sync(0xffffffffu, pR1, o);
                    pW1 += __shfl_xor_sync(0xffffffffu, pW1, o);
                    pH1 += __shfl_xor_sync(0xffffffffu, pH1, o);
                }
                if (lane == 0) {
                    int s = c1 * 8 + warp;
                    sacc[0*512 + s] += pS1; sacc[1*512 + s] += pC1;
                    sacc[2*512 + s] += pR1; sacc[3*512 + s] += pW1;
                    sacc[4*512 + s] += pH1;
                }
            }
        }

        if (cp + 1 < CC / 2) {
            const int nxt = ((cp + 1) & 1) << 1;
            #pragma unroll
            for (int p = 0; p < 2; ++p) {
                float* tn = tile[nxt + p];
                #pragma unroll
                for (int j = 0; j < NFILL; ++j)
                    tn[fidx[j]] = regs[p][j];
            }
        }
    }

    // epilogue: zero-blast then scatter
    const size_t ob = (size_t)(b * 3 * CC) * HW + ((size_t)grow << 7) + c4;
    float* oS = out + ob;
    float* oW = oS + (size_t)CC * HW;
    float* oH = oS + (size_t)2 * CC * HW;
    const float4 z4 = make_float4(0.f, 0.f, 0.f, 0.f);
    #pragma unroll 4
    for (int c = 0; c < CC; ++c) {
        const size_t off = (size_t)c * HW;
        __stcs((float4*)(oS + off), z4);
        __stcs((float4*)(oW + off), z4);
        __stcs((float4*)(oH + off), z4);
    }
    #pragma unroll
    for (int j = 0; j < 4; ++j) {
        oS[(size_t)iS[j] * HW + j] = mS[j];
        oW[(size_t)iW[j] * HW + j] = mW[j];
        oH[(size_t)iH[j] * HW + j] = mH[j];
    }

    // flush bbox partials: thread t<CC reduces its channel's 8 warp slots
    __syncthreads();
    if (t < CC) {
        float a[5];
        #pragma unroll
        for (int q = 0; q < 5; ++q) {
            float v = 0.f;
            #pragma unroll
            for (int w = 0; w < 8; ++w) v += sacc[q*512 + t*8 + w];
            a[q] = v;
        }
        float* dst = g_bbp + ((size_t)(b * CC + t) * 16 + rg) * 5;
        #pragma unroll
        for (int q = 0; q < 5; ++q) dst[q] = a[q];
    }
}

// ---------------------------------------------------------------------------
// K3: reduce 16 row-group partials per (b,c) in fixed order -> bbox cols 1..4.
// ---------------------------------------------------------------------------
__global__ __launch_bounds__(256) void k3_bbox(float* __restrict__ out)
{
    const int bc = blockIdx.x * 256 + threadIdx.x;
    if (bc >= BC) return;
    const float* p = g_bbp + (size_t)bc * 16 * 5;
    float S = 0.f, Sc = 0.f, Sr = 0.f, Sw = 0.f, Sh = 0.f;
    #pragma unroll
    for (int rg = 0; rg < 16; ++rg) {
        S  += p[rg*5+0];
        Sc += p[rg*5+1];
        Sr += p[rg*5+2];
        Sw += p[rg*5+3];
        Sh += p[rg*5+4];
    }
    float ws = Sw / S, hs = Sh / S;
    float x1 = Sc / S - ws * 0.5f;
    float y1 = Sr / S - hs * 0.5f;
    float* bb = out + (size_t)BB * 3 * CC * HW + (size_t)bc * 6;
    bb[1] = x1; bb[2] = y1;
    bb[3] = x1 + ws; bb[4] = y1 + hs;
}

extern "C" void kernel_launch(void* const* d_in, const int* in_sizes, int n_in,
                              void* d_out, int out_size)
{
    const float* x           = (const float*)d_in[0];
    const float* w_bbx       = (const float*)d_in[1];
    const float* w_width     = (const float*)d_in[2];
    const float* w_width_sh  = (const float*)d_in[3];
    const float* w_height    = (const float*)d_in[4];
    const float* w_height_sh = (const float*)d_in[5];
    float* out = (float*)d_out;

    void* enc_addr = nullptr;
    cudaGetSymbolAddress(&enc_addr, g_enc);
    cudaMemsetAsync(enc_addr, 0, BC * sizeof(unsigned));

    k1a_max<<<BC * 4, 256>>>(x);
    k1b_thresh<<<(BC + 255) / 256, 256>>>(out);
    k2_fused<<<256, 256>>>(x, w_bbx, w_width, w_width_sh, w_height, w_height_sh, out);
    k3_bbox<<<(BC + 255) / 256, 256>>>(out);
}

// round 12
// speedup vs baseline: 1.0631x; 1.0631x over previous
#include <cuda_runtime.h>
#include <math.h>

#define BB  16
#define CC  64
#define HH  128
#define WW  128
#define HW  (HH*WW)
#define BC  (BB*CC)

// Per-(b,c) x-space threshold T = logit(sigmoid(max x) - 0.01), from k1.
__device__ float g_T[BC];

__device__ __forceinline__ float sigmoidf_(float v) {
    return 1.0f / (1.0f + expf(-v));
}

// ---------------------------------------------------------------------------
// K1: per-(b,c) plane. max(x) -> ps, threshold T; masked sums -> bbox row.
// (round-9 version)
// ---------------------------------------------------------------------------
__global__ __launch_bounds__(256) void k1_stats(
    const float* __restrict__ x,
    const float* __restrict__ w_bbx,
    const float* __restrict__ w_width,
    const float* __restrict__ w_width_sh,
    const float* __restrict__ w_height,
    const float* __restrict__ w_height_sh,
    float* __restrict__ out)
{
    const int bc = blockIdx.x;
    const int b  = bc / CC;
    const int c  = bc % CC;
    const float* __restrict__ xp = x + (size_t)bc * HW;
    const int t = threadIdx.x;

    float mx = -INFINITY;
    #pragma unroll
    for (int j = 0; j < 16; ++j) {
        float4 v = *(const float4*)(xp + 1024 * j + 4 * t);
        mx = fmaxf(fmaxf(fmaxf(mx, v.x), fmaxf(v.y, v.z)), v.w);
    }
    __shared__ float red[8];
    #pragma unroll
    for (int o = 16; o; o >>= 1) mx = fmaxf(mx, __shfl_xor_sync(0xffffffffu, mx, o));
    if ((t & 31) == 0) red[t >> 5] = mx;
    __syncthreads();
    __shared__ float sT, sps;
    if (t == 0) {
        float v = red[0];
        #pragma unroll
        for (int k = 1; k < 8; ++k) v = fmaxf(v, red[k]);
        float ps = sigmoidf_(v);
        float M  = ps - 0.01f;
        float T;
        if (M > 0.0f) {
            double dM = (double)M;
            T = (float)log(dM / (1.0 - dM));
        } else {
            T = -INFINITY;
        }
        sT = T; sps = ps;
        g_T[bc] = T;
    }
    __syncthreads();
    const float T = sT;

    float cw[11], ch[11];
    #pragma unroll
    for (int k = 0; k < 11; ++k) { cw[k] = w_width[c*11+k]; ch[k] = w_height[c*11+k]; }
    const float s0 = w_bbx[c] * 128.0f;
    const float sW = s0 * w_width_sh[c];
    const float sH = s0 * w_height_sh[c];

    float S = 0.f, Sc = 0.f, Sr = 0.f, Sw = 0.f, Sh = 0.f;
    #pragma unroll
    for (int j = 0; j < 16; ++j) {
        const int i0 = 1024 * j + 4 * t;
        float4 v4 = *(const float4*)(xp + i0);
        float vv[4] = {v4.x, v4.y, v4.z, v4.w};
        if (vv[0] > T || vv[1] > T || vv[2] > T || vv[3] > T) {
            #pragma unroll
            for (int u = 0; u < 4; ++u) {
                float v = vv[u];
                if (v > T) {
                    int i = i0 + u;
                    int row = i >> 7, col = i & 127;
                    S  += v;
                    Sc += (float)col * v;
                    Sr += (float)row * v;
                    float wvv = 0.f;
                    #pragma unroll
                    for (int k = 0; k < 11; ++k) {
                        int cc2 = col - 5 + k;
                        if (cc2 >= 0 && cc2 < WW) wvv = fmaf(xp[(row << 7) + cc2], cw[k], wvv);
                    }
                    float hvv = 0.f;
                    #pragma unroll
                    for (int k = 0; k < 11; ++k) {
                        int rr = row - 5 + k;
                        if (rr >= 0 && rr < HH) hvv = fmaf(xp[(rr << 7) + col], ch[k], hvv);
                    }
                    Sw += wvv * sW * v;
                    Sh += hvv * sH * v;
                }
            }
        }
    }
    __shared__ float racc[5][8];
    #pragma unroll
    for (int o = 16; o; o >>= 1) {
        S  += __shfl_xor_sync(0xffffffffu, S,  o);
        Sc += __shfl_xor_sync(0xffffffffu, Sc, o);
        Sr += __shfl_xor_sync(0xffffffffu, Sr, o);
        Sw += __shfl_xor_sync(0xffffffffu, Sw, o);
        Sh += __shfl_xor_sync(0xffffffffu, Sh, o);
    }
    if ((t & 31) == 0) {
        int w5 = t >> 5;
        racc[0][w5] = S; racc[1][w5] = Sc; racc[2][w5] = Sr; racc[3][w5] = Sw; racc[4][w5] = Sh;
    }
    __syncthreads();
    if (t == 0) {
        float a0=0,a1=0,a2=0,a3=0,a4=0;
        #pragma unroll
        for (int k = 0; k < 8; ++k) { a0+=racc[0][k]; a1+=racc[1][k]; a2+=racc[2][k]; a3+=racc[3][k]; a4+=racc[4][k]; }
        float ws = a3 / a0, hs = a4 / a0;
        float x1 = a1 / a0 - ws * 0.5f;
        float y1 = a2 / a0 - hs * 0.5f;
        float* bb = out + (size_t)BB * 3 * CC * HW + (size_t)bc * 6;
        bb[0] = (float)b; bb[1] = x1; bb[2] = y1;
        bb[3] = x1 + ws;  bb[4] = y1 + hs; bb[5] = sps;
    }
}

// ---------------------------------------------------------------------------
// K2 fused conv/argmax, 2 output rows per thread (vertical-tap reuse):
//   warp w handles rows row0+2w, row0+2w+1; 12 vertical LDS serve both rows.
// Block covers 16 rows -> grid 128 (single wave). Double-buffered tile,
// 1 barrier per channel. Epilogue: zero-blast + scatter.
// ---------------------------------------------------------------------------
#define RG2 16
#define TR2 26            // RG2 + 2*5 halo
#define TP  144           // 8 zero-pad | 128 data | 8 zero-pad
#define NF2 13            // TR2*128 / 256
#define TSZ2 (TR2 * TP)

__global__ __launch_bounds__(256) void k2_fused(
    const float* __restrict__ x,
    const float* __restrict__ w_bbx,
    const float* __restrict__ w_width,
    const float* __restrict__ w_width_sh,
    const float* __restrict__ w_height,
    const float* __restrict__ w_height_sh,
    float* __restrict__ out)
{
    __shared__ float tile[2][TSZ2];
    __shared__ float scw[CC * 11], sch[CC * 11];
    __shared__ float ssW[CC], ssH[CC], sTv[CC];

    const int t    = threadIdx.x;
    const int warp = t >> 5;              // 0..7
    const int c4   = (t & 31) << 2;       // 0..124
    const int b    = blockIdx.y;
    const int row0 = blockIdx.x * RG2;    // grid.x = 8
    const int gr0  = row0 + 2 * warp;     // first of this thread's 2 rows
    const int tr0  = 2 * warp;            // tile row of gr0 - 5... (tile row 0 = row0-5); vert taps start at tile row 2w

    // zero pads once for both buffers
    for (int i = t; i < TSZ2; i += 256) {
        int col = i % TP;
        if (col < 8 || col >= 136) { tile[0][i] = 0.f; tile[1][i] = 0.f; }
    }
    for (int i = t; i < CC * 11; i += 256) { scw[i] = w_width[i]; sch[i] = w_height[i]; }
    if (t < CC) {
        float s0 = w_bbx[t] * 128.0f;
        ssW[t] = s0 * w_width_sh[t];
        ssH[t] = s0 * w_height_sh[t];
        sTv[t] = g_T[b * CC + t];
    }

    // fill staging geometry: NF2 elements per thread cover TR2 x 128
    int   fidx[NF2];
    bool  fok[NF2];
    int   goff[NF2];
    #pragma unroll
    for (int j = 0; j < NF2; ++j) {
        int idx = t + j * 256;
        fidx[j] = (idx >> 7) * TP + 8 + (idx & 127);
        int gr  = row0 - 5 + (idx >> 7);
        fok[j]  = (gr >= 0 && gr < HH);
        goff[j] = (gr << 7) + (idx & 127);
    }

    float regs[NF2];
    const float* xp0 = x + (size_t)(b * CC) * HW;

    // prologue: stage + store channel 0
    {
        #pragma unroll
        for (int j = 0; j < NF2; ++j)
            regs[j] = fok[j] ? __ldg(xp0 + goff[j]) : 0.f;
        #pragma unroll
        for (int j = 0; j < NF2; ++j)
            tile[0][fidx[j]] = regs[j];
    }

    float mS[2][4], mW[2][4], mH[2][4];
    int   iS[2][4], iW[2][4], iH[2][4];
    #pragma unroll
    for (int j = 0; j < 2; ++j)
        #pragma unroll
        for (int q = 0; q < 4; ++q) {
            mS[j][q] = -INFINITY; mW[j][q] = -INFINITY; mH[j][q] = -INFINITY;
            iS[j][q] = 0; iW[j][q] = 0; iH[j][q] = 0;
        }

    for (int c = 0; c < CC; ++c) {
        // prefetch next channel (LDGs overlap barrier + compute)
        if (c + 1 < CC) {
            const float* xp = xp0 + (size_t)(c + 1) * HW;
            #pragma unroll
            for (int j = 0; j < NF2; ++j)
                regs[j] = fok[j] ? __ldg(xp + goff[j]) : 0.f;
        }
        __syncthreads();   // tile[c&1] ready; tile[(c+1)&1] fully consumed

        const float* tl = tile[c & 1];

        // vertical conv: 12 float4 loads serve both output rows
        float a0[4] = {0.f,0.f,0.f,0.f}, a1[4] = {0.f,0.f,0.f,0.f};
        {
            const float* chv = &sch[c * 11];
            #pragma unroll
            for (int k = 0; k < 12; ++k) {
                float4 v = *(const float4*)(&tl[(tr0 + k) * TP + 8 + c4]);
                if (k <= 10) {
                    float ck = chv[k];
                    a0[0] = fmaf(v.x, ck, a0[0]);
                    a0[1] = fmaf(v.y, ck, a0[1]);
                    a0[2] = fmaf(v.z, ck, a0[2]);
                    a0[3] = fmaf(v.w, ck, a0[3]);
                }
                if (k >= 1) {
                    float ck = chv[k - 1];
                    a1[0] = fmaf(v.x, ck, a1[0]);
                    a1[1] = fmaf(v.y, ck, a1[1]);
                    a1[2] = fmaf(v.z, ck, a1[2]);
                    a1[3] = fmaf(v.w, ck, a1[3]);
                }
            }
        }

        const float sWc = ssW[c], sHc = ssH[c], Tc = sTv[c];
        // horizontal conv + score per row
        #pragma unroll
        for (int j = 0; j < 2; ++j) {
            float in[20];
            {
                const float* hrow = &tl[(tr0 + j + 5) * TP + c4];   // data col c4-8
                #pragma unroll
                for (int m = 0; m < 5; ++m) {
                    float4 v = *(const float4*)(hrow + 4 * m);
                    in[4*m+0] = v.x; in[4*m+1] = v.y; in[4*m+2] = v.z; in[4*m+3] = v.w;
                }
            }
            float wv[4] = {0.f,0.f,0.f,0.f};
            #pragma unroll
            for (int k = 0; k < 11; ++k) {
                float ck = scw[c * 11 + k];
                wv[0] = fmaf(in[3 + k], ck, wv[0]);
                wv[1] = fmaf(in[4 + k], ck, wv[1]);
                wv[2] = fmaf(in[5 + k], ck, wv[2]);
                wv[3] = fmaf(in[6 + k], ck, wv[3]);
            }
            const float* av = j ? a1 : a0;
            #pragma unroll
            for (int q = 0; q < 4; ++q) {
                float w_ = wv[q] * sWc;
                float h_ = av[q] * sHc;
                float xv = in[8 + q];
                float s_ = (xv > Tc) ? xv : 0.f;
                if (s_ > mS[j][q]) { mS[j][q] = s_; iS[j][q] = c; }
                if (w_ > mW[j][q]) { mW[j][q] = w_; iW[j][q] = c; }
                if (h_ > mH[j][q]) { mH[j][q] = h_; iH[j][q] = c; }
            }
        }

        if (c + 1 < CC) {
            float* tn = tile[(c + 1) & 1];
            #pragma unroll
            for (int j = 0; j < NF2; ++j)
                tn[fidx[j]] = regs[j];
        }
    }

    // epilogue: zero-blast then scatter (rows gr0, gr0+1)
    const size_t ob = (size_t)(b * 3 * CC) * HW + ((size_t)gr0 << 7) + c4;
    float* oS = out + ob;
    float* oW = oS + (size_t)CC * HW;
    float* oH = oS + (size_t)2 * CC * HW;
    const float4 z4 = make_float4(0.f, 0.f, 0.f, 0.f);
    #pragma unroll 4
    for (int c = 0; c < CC; ++c) {
        const size_t off = (size_t)c * HW;
        __stcs((float4*)(oS + off), z4);
        __stcs((float4*)(oS + off + WW), z4);
        __stcs((float4*)(oW + off), z4);
        __stcs((float4*)(oW + off + WW), z4);
        __stcs((float4*)(oH + off), z4);
        __stcs((float4*)(oH + off + WW), z4);
    }
    #pragma unroll
    for (int j = 0; j < 2; ++j)
        #pragma unroll
        for (int q = 0; q < 4; ++q) {
            oS[(size_t)iS[j][q] * HW + j * WW + q] = mS[j][q];
            oW[(size_t)iW[j][q] * HW + j * WW + q] = mW[j][q];
            oH[(size_t)iH[j][q] * HW + j * WW + q] = mH[j][q];
        }
}

extern "C" void kernel_launch(void* const* d_in, const int* in_sizes, int n_in,
                              void* d_out, int out_size)
{
    const float* x           = (const float*)d_in[0];
    const float* w_bbx       = (const float*)d_in[1];
    const float* w_width     = (const float*)d_in[2];
    const float* w_width_sh  = (const float*)d_in[3];
    const float* w_height    = (const float*)d_in[4];
    const float* w_height_sh = (const float*)d_in[5];
    float* out = (float*)d_out;

    k1_stats<<<BC, 256>>>(x, w_bbx, w_width, w_width_sh, w_height, w_height_sh, out);

    dim3 g2(8, BB);
    k2_fused<<<g2, 256>>>(x, w_bbx, w_width, w_width_sh, w_height, w_height_sh, out);
}

// round 13
// speedup vs baseline: 1.1133x; 1.0472x over previous
#include <cuda_runtime.h>
#include <math.h>

#define BB  16
#define CC  64
#define HH  128
#define WW  128
#define HW  (HH*WW)
#define BC  (BB*CC)

__device__ float g_T[BC];

__device__ __forceinline__ float sigmoidf_(float v) {
    return 1.0f / (1.0f + expf(-v));
}
__device__ __forceinline__ unsigned smem_u32(const void* p) {
    return (unsigned)__cvta_generic_to_shared(p);
}

// ---------------------------------------------------------------------------
// K1: per-(b,c) plane. max(x) -> ps, threshold T; masked sums -> bbox row.
// (round-9 version, unchanged)
// ---------------------------------------------------------------------------
__global__ __launch_bounds__(256) void k1_stats(
    const float* __restrict__ x,
    const float* __restrict__ w_bbx,
    const float* __restrict__ w_width,
    const float* __restrict__ w_width_sh,
    const float* __restrict__ w_height,
    const float* __restrict__ w_height_sh,
    float* __restrict__ out)
{
    const int bc = blockIdx.x;
    const int b  = bc / CC;
    const int c  = bc % CC;
    const float* __restrict__ xp = x + (size_t)bc * HW;
    const int t = threadIdx.x;

    float mx = -INFINITY;
    #pragma unroll
    for (int j = 0; j < 16; ++j) {
        float4 v = *(const float4*)(xp + 1024 * j + 4 * t);
        mx = fmaxf(fmaxf(fmaxf(mx, v.x), fmaxf(v.y, v.z)), v.w);
    }
    __shared__ float red[8];
    #pragma unroll
    for (int o = 16; o; o >>= 1) mx = fmaxf(mx, __shfl_xor_sync(0xffffffffu, mx, o));
    if ((t & 31) == 0) red[t >> 5] = mx;
    __syncthreads();
    __shared__ float sT, sps;
    if (t == 0) {
        float v = red[0];
        #pragma unroll
        for (int k = 1; k < 8; ++k) v = fmaxf(v, red[k]);
        float ps = sigmoidf_(v);
        float M  = ps - 0.01f;
        float T;
        if (M > 0.0f) {
            double dM = (double)M;
            T = (float)log(dM / (1.0 - dM));
        } else {
            T = -INFINITY;
        }
        sT = T; sps = ps;
        g_T[bc] = T;
    }
    __syncthreads();
    const float T = sT;

    float cw[11], ch[11];
    #pragma unroll
    for (int k = 0; k < 11; ++k) { cw[k] = w_width[c*11+k]; ch[k] = w_height[c*11+k]; }
    const float s0 = w_bbx[c] * 128.0f;
    const float sW = s0 * w_width_sh[c];
    const float sH = s0 * w_height_sh[c];

    float S = 0.f, Sc = 0.f, Sr = 0.f, Sw = 0.f, Sh = 0.f;
    #pragma unroll
    for (int j = 0; j < 16; ++j) {
        const int i0 = 1024 * j + 4 * t;
        float4 v4 = *(const float4*)(xp + i0);
        float vv[4] = {v4.x, v4.y, v4.z, v4.w};
        if (vv[0] > T || vv[1] > T || vv[2] > T || vv[3] > T) {
            #pragma unroll
            for (int u = 0; u < 4; ++u) {
                float v = vv[u];
                if (v > T) {
                    int i = i0 + u;
                    int row = i >> 7, col = i & 127;
                    S  += v;
                    Sc += (float)col * v;
                    Sr += (float)row * v;
                    float wvv = 0.f;
                    #pragma unroll
                    for (int k = 0; k < 11; ++k) {
                        int cc2 = col - 5 + k;
                        if (cc2 >= 0 && cc2 < WW) wvv = fmaf(xp[(row << 7) + cc2], cw[k], wvv);
                    }
                    float hvv = 0.f;
                    #pragma unroll
                    for (int k = 0; k < 11; ++k) {
                        int rr = row - 5 + k;
                        if (rr >= 0 && rr < HH) hvv = fmaf(xp[(rr << 7) + col], ch[k], hvv);
                    }
                    Sw += wvv * sW * v;
                    Sh += hvv * sH * v;
                }
            }
        }
    }
    __shared__ float racc[5][8];
    #pragma unroll
    for (int o = 16; o; o >>= 1) {
        S  += __shfl_xor_sync(0xffffffffu, S,  o);
        Sc += __shfl_xor_sync(0xffffffffu, Sc, o);
        Sr += __shfl_xor_sync(0xffffffffu, Sr, o);
        Sw += __shfl_xor_sync(0xffffffffu, Sw, o);
        Sh += __shfl_xor_sync(0xffffffffu, Sh, o);
    }
    if ((t & 31) == 0) {
        int w5 = t >> 5;
        racc[0][w5] = S; racc[1][w5] = Sc; racc[2][w5] = Sr; racc[3][w5] = Sw; racc[4][w5] = Sh;
    }
    __syncthreads();
    if (t == 0) {
        float a0=0,a1=0,a2=0,a3=0,a4=0;
        #pragma unroll
        for (int k = 0; k < 8; ++k) { a0+=racc[0][k]; a1+=racc[1][k]; a2+=racc[2][k]; a3+=racc[3][k]; a4+=racc[4][k]; }
        float ws = a3 / a0, hs = a4 / a0;
        float x1 = a1 / a0 - ws * 0.5f;
        float y1 = a2 / a0 - hs * 0.5f;
        float* bb = out + (size_t)BB * 3 * CC * HW + (size_t)bc * 6;
        bb[0] = (float)b; bb[1] = x1; bb[2] = y1;
        bb[3] = x1 + ws;  bb[4] = y1 + hs; bb[5] = sps;
    }
}

// ---------------------------------------------------------------------------
// K2: 512 threads = two halves over the SAME 16 rows; half h sweeps channels
// [32h, 32h+32) on its own double-buffered tile (cp.async fills, zfill OOB).
// 32 channel iterations, 2 rows/thread vertical-tap reuse, smem merge of the
// two halves' (max,argmax), split zero-blast + scatter epilogue.
// ---------------------------------------------------------------------------
#define RG2 16
#define TR2 26
#define TP  144
#define TSZ2 (TR2 * TP)        // 3744 floats
#define NCHUNK 832             // TR2 * 128 / 4  (float4 chunks per tile)
#define CPH 32                 // channels per half

#define SM_TILES  (4 * TSZ2)
#define SM_SCW    (SM_TILES)
#define SM_SCH    (SM_SCW + CC * 11)
#define SM_SSW    (SM_SCH + CC * 11)
#define SM_SSH    (SM_SSW + CC)
#define SM_STV    (SM_SSH + CC)
#define SM_FLOATS (SM_STV + CC)

__global__ __launch_bounds__(512, 1) void k2_fused(
    const float* __restrict__ x,
    const float* __restrict__ w_bbx,
    const float* __restrict__ w_width,
    const float* __restrict__ w_width_sh,
    const float* __restrict__ w_height,
    const float* __restrict__ w_height_sh,
    float* __restrict__ out)
{
    extern __shared__ float sm[];
    float* tiles = sm;                 // 4 * TSZ2
    float* scw   = sm + SM_SCW;
    float* sch   = sm + SM_SCH;
    float* ssW   = sm + SM_SSW;
    float* ssH   = sm + SM_SSH;
    float* sTv   = sm + SM_STV;

    const int t     = threadIdx.x;      // 0..511
    const int half  = t >> 8;           // 0 / 1
    const int ht    = t & 255;          // index within half
    const int hwarp = ht >> 5;          // 0..7
    const int c4    = (t & 31) << 2;    // 0..124
    const int b     = blockIdx.y;
    const int row0  = blockIdx.x * RG2; // grid.x = 8
    const int gr0   = row0 + 2 * hwarp;
    const int tr0   = 2 * hwarp;
    const int cbase = half * CPH;

    float* mytile = tiles + half * 2 * TSZ2;

    // zero pads once for all 4 buffers
    for (int i = t; i < 4 * TSZ2; i += 512) {
        int col = (i % TSZ2) % TP;
        if (col < 8 || col >= 136) tiles[i] = 0.f;
    }
    for (int i = t; i < CC * 11; i += 512) { scw[i] = w_width[i]; sch[i] = w_height[i]; }
    if (t < CC) {
        float s0 = w_bbx[t] * 128.0f;
        ssW[t] = s0 * w_width_sh[t];
        ssH[t] = s0 * w_height_sh[t];
        sTv[t] = g_T[b * CC + t];
    }

    // fill geometry: 4 float4 chunks per thread cover one tile (26x128)
    int  fdst[4], fsrc[4], fsz[4];
    bool fgo[4];
    #pragma unroll
    for (int j = 0; j < 4; ++j) {
        int chunk = ht + j * 256;
        fgo[j] = (chunk < NCHUNK);
        int rw  = chunk >> 5;
        int cc_ = (chunk & 31) << 2;
        int gr  = row0 - 5 + rw;
        bool ok = (gr >= 0 && gr < HH);
        int grc = ok ? gr : 0;
        fdst[j] = rw * TP + 8 + cc_;
        fsrc[j] = (grc << 7) + cc_;
        fsz[j]  = ok ? 16 : 0;
    }

    const float* xp0 = x + (size_t)(b * CC + cbase) * HW;

    // prologue: async-fill buffer 0 with channel cbase
    #pragma unroll
    for (int j = 0; j < 4; ++j) {
        if (fgo[j]) {
            unsigned d = smem_u32(mytile + fdst[j]);
            asm volatile("cp.async.cg.shared.global [%0], [%1], 16, %2;"
                         :: "r"(d), "l"(xp0 + fsrc[j]), "r"(fsz[j]));
        }
    }
    asm volatile("cp.async.commit_group;");
    asm volatile("cp.async.wait_group 0;");
    __syncthreads();

    float mS[2][4], mW[2][4], mH[2][4];
    int   iS[2][4], iW[2][4], iH[2][4];
    #pragma unroll
    for (int j = 0; j < 2; ++j)
        #pragma unroll
        for (int q = 0; q < 4; ++q) {
            mS[j][q] = -INFINITY; mW[j][q] = -INFINITY; mH[j][q] = -INFINITY;
            iS[j][q] = cbase; iW[j][q] = cbase; iH[j][q] = cbase;
        }

    for (int i = 0; i < CPH; ++i) {
        const int c   = cbase + i;
        const float* tl = mytile + (i & 1) * TSZ2;

        // async-prefetch next channel into the other buffer
        if (i + 1 < CPH) {
            const float* xp = xp0 + (size_t)(i + 1) * HW;
            float* tn = mytile + ((i + 1) & 1) * TSZ2;
            #pragma unroll
            for (int j = 0; j < 4; ++j) {
                if (fgo[j]) {
                    unsigned d = smem_u32(tn + fdst[j]);
                    asm volatile("cp.async.cg.shared.global [%0], [%1], 16, %2;"
                                 :: "r"(d), "l"(xp + fsrc[j]), "r"(fsz[j]));
                }
            }
            asm volatile("cp.async.commit_group;");
        }

        // vertical conv: 12 float4 loads serve both output rows
        float a0[4] = {0.f,0.f,0.f,0.f}, a1[4] = {0.f,0.f,0.f,0.f};
        {
            const float* chv = &sch[c * 11];
            #pragma unroll
            for (int k = 0; k < 12; ++k) {
                float4 v = *(const float4*)(&tl[(tr0 + k) * TP + 8 + c4]);
                if (k <= 10) {
                    float ck = chv[k];
                    a0[0] = fmaf(v.x, ck, a0[0]);
                    a0[1] = fmaf(v.y, ck, a0[1]);
                    a0[2] = fmaf(v.z, ck, a0[2]);
                    a0[3] = fmaf(v.w, ck, a0[3]);
                }
                if (k >= 1) {
                    float ck = chv[k - 1];
                    a1[0] = fmaf(v.x, ck, a1[0]);
                    a1[1] = fmaf(v.y, ck, a1[1]);
                    a1[2] = fmaf(v.z, ck, a1[2]);
                    a1[3] = fmaf(v.w, ck, a1[3]);
                }
            }
        }

        const float sWc = ssW[c], sHc = ssH[c], Tc = sTv[c];
        #pragma unroll
        for (int j = 0; j < 2; ++j) {
            float in[20];
            {
                const float* hrow = &tl[(tr0 + j + 5) * TP + c4];   // data col c4-8
                #pragma unroll
                for (int m = 0; m < 5; ++m) {
                    float4 v = *(const float4*)(hrow + 4 * m);
                    in[4*m+0] = v.x; in[4*m+1] = v.y; in[4*m+2] = v.z; in[4*m+3] = v.w;
                }
            }
            float wv[4] = {0.f,0.f,0.f,0.f};
            #pragma unroll
            for (int k = 0; k < 11; ++k) {
                float ck = scw[c * 11 + k];
                wv[0] = fmaf(in[3 + k], ck, wv[0]);
                wv[1] = fmaf(in[4 + k], ck, wv[1]);
                wv[2] = fmaf(in[5 + k], ck, wv[2]);
                wv[3] = fmaf(in[6 + k], ck, wv[3]);
            }
            const float* av = j ? a1 : a0;
            #pragma unroll
            for (int q = 0; q < 4; ++q) {
                float w_ = wv[q] * sWc;
                float h_ = av[q] * sHc;
                float xv = in[8 + q];
                float s_ = (xv > Tc) ? xv : 0.f;
                if (s_ > mS[j][q]) { mS[j][q] = s_; iS[j][q] = c; }
                if (w_ > mW[j][q]) { mW[j][q] = w_; iW[j][q] = c; }
                if (h_ > mH[j][q]) { mH[j][q] = h_; iH[j][q] = c; }
            }
        }

        if (i + 1 < CPH) asm volatile("cp.async.wait_group 0;");
        __syncthreads();
    }

    // ---------------- merge halves via smem (tiles region is dead) ----------
    float* mb = tiles + ht * 48;   // 256 * 48 floats = 12288 <= 4*TSZ2
    if (half == 1) {
        #pragma unroll
        for (int j = 0; j < 2; ++j)
            #pragma unroll
            for (int q = 0; q < 4; ++q) {
                int o = (j * 4 + q) * 6;
                mb[o+0] = mS[j][q]; mb[o+1] = __int_as_float(iS[j][q]);
                mb[o+2] = mW[j][q]; mb[o+3] = __int_as_float(iW[j][q]);
                mb[o+4] = mH[j][q]; mb[o+5] = __int_as_float(iH[j][q]);
            }
    }
    __syncthreads();
    if (half == 0) {
        #pragma unroll
        for (int j = 0; j < 2; ++j)
            #pragma unroll
            for (int q = 0; q < 4; ++q) {
                int o = (j * 4 + q) * 6;
                float bv;
                bv = mb[o+0]; if (bv > mS[j][q]) { mS[j][q] = bv; iS[j][q] = __float_as_int(mb[o+1]); }
                bv = mb[o+2]; if (bv > mW[j][q]) { mW[j][q] = bv; iW[j][q] = __float_as_int(mb[o+3]); }
                bv = mb[o+4]; if (bv > mH[j][q]) { mH[j][q] = bv; iH[j][q] = __float_as_int(mb[o+5]); }
                mb[o+0] = mS[j][q]; mb[o+1] = __int_as_float(iS[j][q]);
                mb[o+2] = mW[j][q]; mb[o+3] = __int_as_float(iW[j][q]);
                mb[o+4] = mH[j][q]; mb[o+5] = __int_as_float(iH[j][q]);
            }
    }
    __syncthreads();
    // both halves load merged results for their pixel set
    #pragma unroll
    for (int j = 0; j < 2; ++j)
        #pragma unroll
        for (int q = 0; q < 4; ++q) {
            int o = (j * 4 + q) * 6;
            mS[j][q] = mb[o+0]; iS[j][q] = __float_as_int(mb[o+1]);
            mW[j][q] = mb[o+2]; iW[j][q] = __float_as_int(mb[o+3]);
            mH[j][q] = mb[o+4]; iH[j][q] = __float_as_int(mb[o+5]);
        }

    // ----- epilogue: zero-blast own channel range, then scatter own range ---
    const size_t ob = (size_t)(b * 3 * CC) * HW + ((size_t)gr0 << 7) + c4;
    float* oS = out + ob;
    float* oW = oS + (size_t)CC * HW;
    float* oH = oS + (size_t)2 * CC * HW;
    const float4 z4 = make_float4(0.f, 0.f, 0.f, 0.f);
    #pragma unroll 4
    for (int c = 0; c < CPH; ++c) {
        const size_t off = (size_t)(cbase + c) * HW;
        __stcs((float4*)(oS + off), z4);
        __stcs((float4*)(oS + off + WW), z4);
        __stcs((float4*)(oW + off), z4);
        __stcs((float4*)(oW + off + WW), z4);
        __stcs((float4*)(oH + off), z4);
        __stcs((float4*)(oH + off + WW), z4);
    }
    #pragma unroll
    for (int j = 0; j < 2; ++j)
        #pragma unroll
        for (int q = 0; q < 4; ++q) {
            if (iS[j][q] >= cbase && iS[j][q] < cbase + CPH)
                oS[(size_t)iS[j][q] * HW + j * WW + q] = mS[j][q];
            if (iW[j][q] >= cbase && iW[j][q] < cbase + CPH)
                oW[(size_t)iW[j][q] * HW + j * WW + q] = mW[j][q];
            if (iH[j][q] >= cbase && iH[j][q] < cbase + CPH)
                oH[(size_t)iH[j][q] * HW + j * WW + q] = mH[j][q];
        }
}

extern "C" void kernel_launch(void* const* d_in, const int* in_sizes, int n_in,
                              void* d_out, int out_size)
{
    const float* x           = (const float*)d_in[0];
    const float* w_bbx       = (const float*)d_in[1];
    const float* w_width     = (const float*)d_in[2];
    const float* w_width_sh  = (const float*)d_in[3];
    const float* w_height    = (const float*)d_in[4];
    const float* w_height_sh = (const float*)d_in[5];
    float* out = (float*)d_out;

    k1_stats<<<BC, 256>>>(x, w_bbx, w_width, w_width_sh, w_height, w_height_sh, out);

    const int smem_bytes = SM_FLOATS * (int)sizeof(float);
    cudaFuncSetAttribute(k2_fused, cudaFuncAttributeMaxDynamicSharedMemorySize, smem_bytes);
    dim3 g2(8, BB);
    k2_fused<<<g2, 512, smem_bytes>>>(x, w_bbx, w_width, w_width_sh, w_height, w_height_sh, out);
}

// round 14
// speedup vs baseline: 1.3573x; 1.2191x over previous
#include <cuda_runtime.h>
#include <math.h>

#define BB  16
#define CC  64
#define HH  128
#define WW  128
#define HW  (HH*WW)
#define BC  (BB*CC)

__device__ float g_T[BC];

__device__ __forceinline__ float sigmoidf_(float v) {
    return 1.0f / (1.0f + expf(-v));
}
__device__ __forceinline__ unsigned smem_u32(const void* p) {
    return (unsigned)__cvta_generic_to_shared(p);
}

// ---------------------------------------------------------------------------
// K1: per-(b,c) plane. max(x) -> ps, threshold T; masked sums -> bbox row.
// (round-9 version, unchanged)
// ---------------------------------------------------------------------------
__global__ __launch_bounds__(256) void k1_stats(
    const float* __restrict__ x,
    const float* __restrict__ w_bbx,
    const float* __restrict__ w_width,
    const float* __restrict__ w_width_sh,
    const float* __restrict__ w_height,
    const float* __restrict__ w_height_sh,
    float* __restrict__ out)
{
    const int bc = blockIdx.x;
    const int b  = bc / CC;
    const int c  = bc % CC;
    const float* __restrict__ xp = x + (size_t)bc * HW;
    const int t = threadIdx.x;

    float mx = -INFINITY;
    #pragma unroll
    for (int j = 0; j < 16; ++j) {
        float4 v = *(const float4*)(xp + 1024 * j + 4 * t);
        mx = fmaxf(fmaxf(fmaxf(mx, v.x), fmaxf(v.y, v.z)), v.w);
    }
    __shared__ float red[8];
    #pragma unroll
    for (int o = 16; o; o >>= 1) mx = fmaxf(mx, __shfl_xor_sync(0xffffffffu, mx, o));
    if ((t & 31) == 0) red[t >> 5] = mx;
    __syncthreads();
    __shared__ float sT, sps;
    if (t == 0) {
        float v = red[0];
        #pragma unroll
        for (int k = 1; k < 8; ++k) v = fmaxf(v, red[k]);
        float ps = sigmoidf_(v);
        float M  = ps - 0.01f;
        float T;
        if (M > 0.0f) {
            double dM = (double)M;
            T = (float)log(dM / (1.0 - dM));
        } else {
            T = -INFINITY;
        }
        sT = T; sps = ps;
        g_T[bc] = T;
    }
    __syncthreads();
    const float T = sT;

    float cw[11], ch[11];
    #pragma unroll
    for (int k = 0; k < 11; ++k) { cw[k] = w_width[c*11+k]; ch[k] = w_height[c*11+k]; }
    const float s0 = w_bbx[c] * 128.0f;
    const float sW = s0 * w_width_sh[c];
    const float sH = s0 * w_height_sh[c];

    float S = 0.f, Sc = 0.f, Sr = 0.f, Sw = 0.f, Sh = 0.f;
    #pragma unroll
    for (int j = 0; j < 16; ++j) {
        const int i0 = 1024 * j + 4 * t;
        float4 v4 = *(const float4*)(xp + i0);
        float vv[4] = {v4.x, v4.y, v4.z, v4.w};
        if (vv[0] > T || vv[1] > T || vv[2] > T || vv[3] > T) {
            #pragma unroll
            for (int u = 0; u < 4; ++u) {
                float v = vv[u];
                if (v > T) {
                    int i = i0 + u;
                    int row = i >> 7, col = i & 127;
                    S  += v;
                    Sc += (float)col * v;
                    Sr += (float)row * v;
                    float wvv = 0.f;
                    #pragma unroll
                    for (int k = 0; k < 11; ++k) {
                        int cc2 = col - 5 + k;
                        if (cc2 >= 0 && cc2 < WW) wvv = fmaf(xp[(row << 7) + cc2], cw[k], wvv);
                    }
                    float hvv = 0.f;
                    #pragma unroll
                    for (int k = 0; k < 11; ++k) {
                        int rr = row - 5 + k;
                        if (rr >= 0 && rr < HH) hvv = fmaf(xp[(rr << 7) + col], ch[k], hvv);
                    }
                    Sw += wvv * sW * v;
                    Sh += hvv * sH * v;
                }
            }
        }
    }
    __shared__ float racc[5][8];
    #pragma unroll
    for (int o = 16; o; o >>= 1) {
        S  += __shfl_xor_sync(0xffffffffu, S,  o);
        Sc += __shfl_xor_sync(0xffffffffu, Sc, o);
        Sr += __shfl_xor_sync(0xffffffffu, Sr, o);
        Sw += __shfl_xor_sync(0xffffffffu, Sw, o);
        Sh += __shfl_xor_sync(0xffffffffu, Sh, o);
    }
    if ((t & 31) == 0) {
        int w5 = t >> 5;
        racc[0][w5] = S; racc[1][w5] = Sc; racc[2][w5] = Sr; racc[3][w5] = Sw; racc[4][w5] = Sh;
    }
    __syncthreads();
    if (t == 0) {
        float a0=0,a1=0,a2=0,a3=0,a4=0;
        #pragma unroll
        for (int k = 0; k < 8; ++k) { a0+=racc[0][k]; a1+=racc[1][k]; a2+=racc[2][k]; a3+=racc[3][k]; a4+=racc[4][k]; }
        float ws = a3 / a0, hs = a4 / a0;
        float x1 = a1 / a0 - ws * 0.5f;
        float y1 = a2 / a0 - hs * 0.5f;
        float* bb = out + (size_t)BB * 3 * CC * HW + (size_t)bc * 6;
        bb[0] = (float)b; bb[1] = x1; bb[2] = y1;
        bb[3] = x1 + ws;  bb[4] = y1 + hs; bb[5] = sps;
    }
}

// ---------------------------------------------------------------------------
// K2: two 256-thread halves over the SAME 16 rows; half h sweeps channels
// [32h, 32h+32) on a 3-buffer cp.async ring (wait_group 1 -> fills get 2
// iterations to land). The zero-blast of the output is interleaved into the
// channel loop (iteration i zeroes channel cbase+i), overlapping ~30us of
// DRAM store time with compute. Final epilogue: merge halves + scatter only.
// ---------------------------------------------------------------------------
#define RG2 16
#define TR2 26
#define TP  144
#define TSZ2 (TR2 * TP)        // 3744 floats
#define NCHUNK 832             // TR2 * 128 / 4
#define CPH 32
#define NBUF 3

#define SM_TILES  (2 * NBUF * TSZ2)
#define SM_SCW    (SM_TILES)
#define SM_SCH    (SM_SCW + CC * 11)
#define SM_SSW    (SM_SCH + CC * 11)
#define SM_SSH    (SM_SSW + CC)
#define SM_STV    (SM_SSH + CC)
#define SM_FLOATS (SM_STV + CC)

__global__ __launch_bounds__(512, 1) void k2_fused(
    const float* __restrict__ x,
    const float* __restrict__ w_bbx,
    const float* __restrict__ w_width,
    const float* __restrict__ w_width_sh,
    const float* __restrict__ w_height,
    const float* __restrict__ w_height_sh,
    float* __restrict__ out)
{
    extern __shared__ float sm[];
    float* tiles = sm;                 // 2 halves x NBUF x TSZ2
    float* scw   = sm + SM_SCW;
    float* sch   = sm + SM_SCH;
    float* ssW   = sm + SM_SSW;
    float* ssH   = sm + SM_SSH;
    float* sTv   = sm + SM_STV;

    const int t     = threadIdx.x;      // 0..511
    const int half  = t >> 8;           // 0 / 1
    const int ht    = t & 255;
    const int hwarp = ht >> 5;          // 0..7
    const int c4    = (t & 31) << 2;    // 0..124
    const int b     = blockIdx.y;
    const int row0  = blockIdx.x * RG2; // grid.x = 8
    const int gr0   = row0 + 2 * hwarp;
    const int tr0   = 2 * hwarp;
    const int cbase = half * CPH;

    float* mytile = tiles + half * NBUF * TSZ2;

    // zero pads once for all buffers
    for (int i = t; i < 2 * NBUF * TSZ2; i += 512) {
        int col = (i % TSZ2) % TP;
        if (col < 8 || col >= 136) tiles[i] = 0.f;
    }
    for (int i = t; i < CC * 11; i += 512) { scw[i] = w_width[i]; sch[i] = w_height[i]; }
    if (t < CC) {
        float s0 = w_bbx[t] * 128.0f;
        ssW[t] = s0 * w_width_sh[t];
        ssH[t] = s0 * w_height_sh[t];
        sTv[t] = g_T[b * CC + t];
    }

    // fill geometry: 4 float4 chunks per thread cover one tile (26x128)
    int  fdst[4], fsrc[4], fsz[4];
    bool fgo[4];
    #pragma unroll
    for (int j = 0; j < 4; ++j) {
        int chunk = ht + j * 256;
        fgo[j] = (chunk < NCHUNK);
        int rw  = chunk >> 5;
        int cc_ = (chunk & 31) << 2;
        int gr  = row0 - 5 + rw;
        bool ok = (gr >= 0 && gr < HH);
        int grc = ok ? gr : 0;
        fdst[j] = rw * TP + 8 + cc_;
        fsrc[j] = (grc << 7) + cc_;
        fsz[j]  = ok ? 16 : 0;
    }

    const float* xp0 = x + (size_t)(b * CC + cbase) * HW;

    // prologue: fill buffers 0 and 1 (separate groups)
    #pragma unroll
    for (int p = 0; p < 2; ++p) {
        const float* xp = xp0 + (size_t)p * HW;
        float* tn = mytile + p * TSZ2;
        #pragma unroll
        for (int j = 0; j < 4; ++j) {
            if (fgo[j]) {
                unsigned d = smem_u32(tn + fdst[j]);
                asm volatile("cp.async.cg.shared.global [%0], [%1], 16, %2;"
                             :: "r"(d), "l"(xp + fsrc[j]), "r"(fsz[j]));
            }
        }
        asm volatile("cp.async.commit_group;");
    }

    float mS[2][4], mW[2][4], mH[2][4];
    int   iS[2][4], iW[2][4], iH[2][4];
    #pragma unroll
    for (int j = 0; j < 2; ++j)
        #pragma unroll
        for (int q = 0; q < 4; ++q) {
            mS[j][q] = -INFINITY; mW[j][q] = -INFINITY; mH[j][q] = -INFINITY;
            iS[j][q] = cbase; iW[j][q] = cbase; iH[j][q] = cbase;
        }

    // output base pointers (for interleaved zero-blast)
    const size_t ob = (size_t)(b * 3 * CC) * HW + ((size_t)gr0 << 7) + c4;
    float* oS = out + ob;
    float* oW = oS + (size_t)CC * HW;
    float* oH = oS + (size_t)2 * CC * HW;
    const float4 z4 = make_float4(0.f, 0.f, 0.f, 0.f);

    int slot = 0;  // buffer of current channel
    for (int i = 0; i < CPH; ++i) {
        const int c = cbase + i;

        // wait until fill(i) complete (fill(i+1) may still be in flight)
        asm volatile("cp.async.wait_group 1;");
        __syncthreads();   // everyone done reading slot of channel i-1 & fill visible

        // issue fill(i+2) into the slot channel i-1 occupied
        {
            const float* xp = xp0 + (size_t)(i + 2) * HW;
            float* tn = mytile + ((slot + 2) % NBUF) * TSZ2;
            if (i + 2 < CPH) {
                #pragma unroll
                for (int j = 0; j < 4; ++j) {
                    if (fgo[j]) {
                        unsigned d = smem_u32(tn + fdst[j]);
                        asm volatile("cp.async.cg.shared.global [%0], [%1], 16, %2;"
                                     :: "r"(d), "l"(xp + fsrc[j]), "r"(fsz[j]));
                    }
                }
            }
            asm volatile("cp.async.commit_group;");   // (possibly empty group)
        }

        const float* tl = mytile + slot * TSZ2;

        // interleaved zero-blast: channel c's 6 output row-chunks
        {
            const size_t off = (size_t)c * HW;
            __stcs((float4*)(oS + off), z4);
            __stcs((float4*)(oS + off + WW), z4);
            __stcs((float4*)(oW + off), z4);
            __stcs((float4*)(oW + off + WW), z4);
            __stcs((float4*)(oH + off), z4);
            __stcs((float4*)(oH + off + WW), z4);
        }

        // vertical conv: 12 float4 loads serve both output rows
        float a0[4] = {0.f,0.f,0.f,0.f}, a1[4] = {0.f,0.f,0.f,0.f};
        {
            const float* chv = &sch[c * 11];
            #pragma unroll
            for (int k = 0; k < 12; ++k) {
                float4 v = *(const float4*)(&tl[(tr0 + k) * TP + 8 + c4]);
                if (k <= 10) {
                    float ck = chv[k];
                    a0[0] = fmaf(v.x, ck, a0[0]);
                    a0[1] = fmaf(v.y, ck, a0[1]);
                    a0[2] = fmaf(v.z, ck, a0[2]);
                    a0[3] = fmaf(v.w, ck, a0[3]);
                }
                if (k >= 1) {
                    float ck = chv[k - 1];
                    a1[0] = fmaf(v.x, ck, a1[0]);
                    a1[1] = fmaf(v.y, ck, a1[1]);
                    a1[2] = fmaf(v.z, ck, a1[2]);
                    a1[3] = fmaf(v.w, ck, a1[3]);
                }
            }
        }

        const float sWc = ssW[c], sHc = ssH[c], Tc = sTv[c];
        #pragma unroll
        for (int j = 0; j < 2; ++j) {
            float in[20];
            {
                const float* hrow = &tl[(tr0 + j + 5) * TP + c4];   // data col c4-8
                #pragma unroll
                for (int m = 0; m < 5; ++m) {
                    float4 v = *(const float4*)(hrow + 4 * m);
                    in[4*m+0] = v.x; in[4*m+1] = v.y; in[4*m+2] = v.z; in[4*m+3] = v.w;
                }
            }
            float wv[4] = {0.f,0.f,0.f,0.f};
            #pragma unroll
            for (int k = 0; k < 11; ++k) {
                float ck = scw[c * 11 + k];
                wv[0] = fmaf(in[3 + k], ck, wv[0]);
                wv[1] = fmaf(in[4 + k], ck, wv[1]);
                wv[2] = fmaf(in[5 + k], ck, wv[2]);
                wv[3] = fmaf(in[6 + k], ck, wv[3]);
            }
            const float* av = j ? a1 : a0;
            #pragma unroll
            for (int q = 0; q < 4; ++q) {
                float w_ = wv[q] * sWc;
                float h_ = av[q] * sHc;
                float xv = in[8 + q];
                float s_ = (xv > Tc) ? xv : 0.f;
                if (s_ > mS[j][q]) { mS[j][q] = s_; iS[j][q] = c; }
                if (w_ > mW[j][q]) { mW[j][q] = w_; iW[j][q] = c; }
                if (h_ > mH[j][q]) { mH[j][q] = h_; iH[j][q] = c; }
            }
        }

        slot = (slot + 1) % NBUF;
    }
    __syncthreads();   // all warps done with tiles (reused as merge buffer)

    // ---------------- merge halves via smem (tiles region is dead) ----------
    float* mb = tiles + ht * 48;
    if (half == 1) {
        #pragma unroll
        for (int j = 0; j < 2; ++j)
            #pragma unroll
            for (int q = 0; q < 4; ++q) {
                int o = (j * 4 + q) * 6;
                mb[o+0] = mS[j][q]; mb[o+1] = __int_as_float(iS[j][q]);
                mb[o+2] = mW[j][q]; mb[o+3] = __int_as_float(iW[j][q]);
                mb[o+4] = mH[j][q]; mb[o+5] = __int_as_float(iH[j][q]);
            }
    }
    __syncthreads();
    if (half == 0) {
        #pragma unroll
        for (int j = 0; j < 2; ++j)
            #pragma unroll
            for (int q = 0; q < 4; ++q) {
                int o = (j * 4 + q) * 6;
                float bv;
                bv = mb[o+0]; if (bv > mS[j][q]) { mS[j][q] = bv; iS[j][q] = __float_as_int(mb[o+1]); }
                bv = mb[o+2]; if (bv > mW[j][q]) { mW[j][q] = bv; iW[j][q] = __float_as_int(mb[o+3]); }
                bv = mb[o+4]; if (bv > mH[j][q]) { mH[j][q] = bv; iH[j][q] = __float_as_int(mb[o+5]); }
                mb[o+0] = mS[j][q]; mb[o+1] = __int_as_float(iS[j][q]);
                mb[o+2] = mW[j][q]; mb[o+3] = __int_as_float(iW[j][q]);
                mb[o+4] = mH[j][q]; mb[o+5] = __int_as_float(iH[j][q]);
            }
    }
    __syncthreads();
    #pragma unroll
    for (int j = 0; j < 2; ++j)
        #pragma unroll
        for (int q = 0; q < 4; ++q) {
            int o = (j * 4 + q) * 6;
            mS[j][q] = mb[o+0]; iS[j][q] = __float_as_int(mb[o+1]);
            mW[j][q] = mb[o+2]; iW[j][q] = __float_as_int(mb[o+3]);
            mH[j][q] = mb[o+4]; iH[j][q] = __float_as_int(mb[o+5]);
        }

    // ----- scatter own channel range (zeros already written in-loop) --------
    #pragma unroll
    for (int j = 0; j < 2; ++j)
        #pragma unroll
        for (int q = 0; q < 4; ++q) {
            if (iS[j][q] >= cbase && iS[j][q] < cbase + CPH)
                oS[(size_t)iS[j][q] * HW + j * WW + q] = mS[j][q];
            if (iW[j][q] >= cbase && iW[j][q] < cbase + CPH)
                oW[(size_t)iW[j][q] * HW + j * WW + q] = mW[j][q];
            if (iH[j][q] >= cbase && iH[j][q] < cbase + CPH)
                oH[(size_t)iH[j][q] * HW + j * WW + q] = mH[j][q];
        }
}

extern "C" void kernel_launch(void* const* d_in, const int* in_sizes, int n_in,
                              void* d_out, int out_size)
{
    const float* x           = (const float*)d_in[0];
    const float* w_bbx       = (const float*)d_in[1];
    const float* w_width     = (const float*)d_in[2];
    const float* w_width_sh  = (const float*)d_in[3];
    const float* w_height    = (const float*)d_in[4];
    const float* w_height_sh = (const float*)d_in[5];
    float* out = (float*)d_out;

    k1_stats<<<BC, 256>>>(x, w_bbx, w_width, w_width_sh, w_height, w_height_sh, out);

    const int smem_bytes = SM_FLOATS * (int)sizeof(float);
    cudaFuncSetAttribute(k2_fused, cudaFuncAttributeMaxDynamicSharedMemorySize, smem_bytes);
    dim3 g2(8, BB);
    k2_fused<<<g2, 512, smem_bytes>>>(x, w_bbx, w_width, w_width_sh, w_height, w_height_sh, out);
}